// round 10
// baseline (speedup 1.0000x reference)
#include <cuda_runtime.h>
#include <math.h>
#include <stdint.h>

#define IM     256
#define MTOT   184320
#define ORTHO  (1.0f/256.0f)
#define NSPLIT 72
#define ADJ_MPER (MTOT/NSPLIT)   // 2560 m per split
#define ADJ_ST   (ADJ_MPER/16)   // 160 stages (16 m = 32 k per stage)

// ---------------- static scratch (allocation-free) -------------------------
__device__ float  g_Bf[512*512];                    // fwd B operand (1 MB)
__device__ float2 g_S1x[MTOT], g_S8x[MTOT];
__device__ float2 g_S1y[MTOT], g_S8y[MTOT], g_S64y[MTOT], g_S128y[MTOT];
__device__ float2 g_PCH[(size_t)MTOT*16];   // conj(T0x * S16x^j), j 0..15 (fwd A base)
__device__ float2 g_PXU[(size_t)MTOT*16];   // [ut=0]: T0x*S1x^s ; [ut=1]: S1x^s
__device__ float2 g_PYB[(size_t)MTOT*16];   // [b=0]: S1y^s ; [b=1]: S128y*S1y^s
__device__ float2 g_E0[MTOT];               // kdc * e^{-i 128 ky}
__device__ float  g_P[(size_t)8*NSPLIT*128*128];    // adjoint partials (37.7 MB)

// ---------------- helpers --------------------------------------------------
__device__ __forceinline__ float2 cmulf(float2 a, float2 b) {
    return make_float2(a.x*b.x - a.y*b.y, a.x*b.y + a.y*b.x);
}
__device__ __forceinline__ float2 conjf(float2 a) { return make_float2(a.x, -a.y); }
__device__ __forceinline__ uint32_t tf32u(float x) {
    uint32_t r; asm("cvt.rna.tf32.f32 %0, %1;" : "=r"(r) : "f"(x)); return r;
}
__device__ __forceinline__ float tf32f(float x) {
    uint32_t r; asm("cvt.rna.tf32.f32 %0, %1;" : "=r"(r) : "f"(x));
    return __uint_as_float(r);
}
__device__ __forceinline__ float2 cpow4(float2 b, int e) {
    float2 r = make_float2(1.f, 0.f);
#pragma unroll
    for (int i = 0; i < 4; i++) { if (e & (1 << i)) r = cmulf(r, b); b = cmulf(b, b); }
    return r;
}
__device__ __forceinline__ void mma8(float* d, const uint32_t* a, const uint32_t* b) {
    asm volatile(
        "mma.sync.aligned.m16n8k8.row.col.f32.tf32.tf32.f32 "
        "{%0,%1,%2,%3}, {%4,%5,%6,%7}, {%8,%9}, {%0,%1,%2,%3};"
        : "+f"(d[0]), "+f"(d[1]), "+f"(d[2]), "+f"(d[3])
        : "r"(a[0]), "r"(a[1]), "r"(a[2]), "r"(a[3]), "r"(b[0]), "r"(b[1]));
}
__device__ __forceinline__ uint32_t su32(const void* p) {
    uint32_t a; asm("{ .reg .u64 t; cvta.to.shared.u64 t, %1; cvt.u32.u64 %0, t; }" : "=r"(a) : "l"(p));
    return a;
}
__device__ __forceinline__ void cp16(uint32_t saddr, const void* g) {
    asm volatile("cp.async.cg.shared.global [%0], [%1], 16;" :: "r"(saddr), "l"(g));
}

// ---------------- prep: per-m phase/power tables ---------------------------
__global__ __launch_bounds__(256) void prep_tab(const float* __restrict__ kxs,
                                                const float* __restrict__ kys)
{
    int m = blockIdx.x * 256 + threadIdx.x;
    float s, c;
    float kx = kxs[m], ky = kys[m];
    sincosf(kx, &s, &c);
    float2 S1 = make_float2(c, s);
    float2 S2 = cmulf(S1,S1), S4 = cmulf(S2,S2), S8 = cmulf(S4,S4);
    float2 S16 = cmulf(S8,S8), S32 = cmulf(S16,S16), S64 = cmulf(S32,S32);
    float2 S128 = cmulf(S64,S64);
    float2 T0 = conjf(S128);                         // e^{-i 128 kx}
    g_S1x[m] = S1; g_S8x[m] = S8;
    float2 q = T0;
#pragma unroll
    for (int j = 0; j < 16; j++) { g_PCH[(size_t)m*16 + j] = conjf(q); q = cmulf(q, S16); }
    float2 p = make_float2(1.f, 0.f);
#pragma unroll
    for (int s8 = 0; s8 < 8; s8++) {
        g_PXU[(size_t)m*16 + s8]     = cmulf(T0, p);   // ut=0
        g_PXU[(size_t)m*16 + 8 + s8] = p;              // ut=1
        p = cmulf(p, S1);
    }
    sincosf(ky, &s, &c);
    S1 = make_float2(c, s);
    S2 = cmulf(S1,S1); S4 = cmulf(S2,S2); S8 = cmulf(S4,S4);
    S16 = cmulf(S8,S8); S32 = cmulf(S16,S16); S64 = cmulf(S32,S32);
    S128 = cmulf(S64,S64);
    g_S1y[m] = S1; g_S8y[m] = S8; g_S64y[m] = S64; g_S128y[m] = S128;
    p = make_float2(1.f, 0.f);
#pragma unroll
    for (int s8 = 0; s8 < 8; s8++) {
        g_PYB[(size_t)m*16 + s8]     = p;
        g_PYB[(size_t)m*16 + 8 + s8] = cmulf(S128, p);
        p = cmulf(p, S1);
    }
}

// B_f[k][n]: n<256 (v=n): k<256 -> R[k][v], else -I[k-256][v]
//            n>=256:      k<256 -> I[k][v], else  R[k-256][v]
__global__ __launch_bounds__(256) void prep_bf(const float2* __restrict__ img)
{
    int idx = blockIdx.x * 256 + threadIdx.x;
    int k = idx >> 9, n = idx & 511;
    int v = n & 255, u = k & 255;
    float2 g = img[u * 256 + v];
    float val = (n < 256) ? ((k < 256) ? g.x : -g.y)
                          : ((k < 256) ? g.y :  g.x);
    g_Bf[idx] = tf32f(val);
}

// ---------------------------------------------------------------------------
// Forward GEMM, software-pipelined: per stage, gen A(s+1) into alt buffer +
// cp.async B(s+1) while MMA(s) runs; single __syncthreads per stage.
// CTA: 128 m x (N=512 over 4 nt), 128 threads, warp tile 64x64.
// Fused Ey-reduce at each nt boundary; blend epilogue -> g_E0.
// ---------------------------------------------------------------------------
__global__ __launch_bounds__(128)
void fwd_gemm(const float2* __restrict__ yrad, const float* __restrict__ lamp,
              const float* __restrict__ kxs, const float* __restrict__ kys)
{
    extern __shared__ uint32_t sh[];
    uint32_t* As = sh;                       // 2 x 128*36
    uint32_t* Bs = sh + 9216;                // 2 x 32*136
    float2*   t_acc = (float2*)(sh + 9216 + 8704);  // [2][128]

    const int tid = threadIdx.x, lane = tid & 31, wid = tid >> 5;
    const int wm = wid >> 1, wn = wid & 1;
    const int m0 = blockIdx.x * 128;
    const int gh = tid & 1, grow = tid >> 1;

    const float2 S1c0 = conjf(g_S1x[m0 + grow]);
    const float2 S1c1 = conjf(g_S1x[m0 + grow + 64]);

    t_acc[tid]       = make_float2(0.f, 0.f);
    t_acc[128 + tid] = make_float2(0.f, 0.f);

    float acc[4][8][4];
#pragma unroll
    for (int i = 0; i < 4; i++)
#pragma unroll
        for (int j = 0; j < 8; j++)
#pragma unroll
            for (int q = 0; q < 4; q++) acc[i][j][q] = 0.f;

    // ---- prologue: stage 0 ----
    float2 bA0 = g_PCH[(size_t)(m0 + grow)      * 16 + gh];
    float2 bA1 = g_PCH[(size_t)(m0 + grow + 64) * 16 + gh];
    {
        const uint32_t sb = su32(Bs);
#pragma unroll
        for (int it = 0; it < 8; it++) {
            int idx = it * 128 + tid, r = idx >> 5, c4 = idx & 31;
            cp16(sb + (r * 136 + c4 * 4) * 4, g_Bf + (size_t)r * 512 + c4 * 4);
        }
        asm volatile("cp.async.commit_group;");
    }
    {   // gen A(0) into buf 0 (ch=0 -> iscos)
        float2 cur = bA0;
        const int rb = grow * 36 + 16 * gh;
#pragma unroll
        for (int q = 0; q < 16; q++) { As[rb + q] = tf32u(cur.x); cur = cmulf(cur, S1c0); }
        cur = bA1;
        const int rb1 = (grow + 64) * 36 + 16 * gh;
#pragma unroll
        for (int q = 0; q < 16; q++) { As[rb1 + q] = tf32u(cur.x); cur = cmulf(cur, S1c1); }
    }
    bA0 = g_PCH[(size_t)(m0 + grow)      * 16 + 2 + gh];   // bases for ls=1 (j=2ch+gh)
    bA1 = g_PCH[(size_t)(m0 + grow + 64) * 16 + 2 + gh];
    asm volatile("cp.async.wait_group 0;");
    __syncthreads();

    for (int ls = 0; ls < 64; ls++) {
        const int buf = ls & 1;
        const int nt = ls >> 4, ch = ls & 15;
        // ---- gen stage ls+1 into alt buffers (overlaps with MMA below) ----
        if (ls < 63) {
            const int lsn = ls + 1, chn = lsn & 15, ntn = lsn >> 4;
            {   // cp.async B(ls+1)
                const uint32_t sb = su32(Bs) + (buf ^ 1) * 4352 * 4;
#pragma unroll
                for (int it = 0; it < 8; it++) {
                    int idx = it * 128 + tid, r = idx >> 5, c4 = idx & 31;
                    cp16(sb + (r * 136 + c4 * 4) * 4,
                         g_Bf + (size_t)(32 * chn + r) * 512 + ntn * 128 + c4 * 4);
                }
                asm volatile("cp.async.commit_group;");
            }
            {   // gen A(ls+1)
                uint32_t* Ap = As + (buf ^ 1) * 4608;
                const bool iscos = (chn < 8);
                float2 cur = bA0;
                const int rb = grow * 36 + 16 * gh;
#pragma unroll
                for (int q = 0; q < 16; q++) {
                    Ap[rb + q] = tf32u(iscos ? cur.x : cur.y);
                    cur = cmulf(cur, S1c0);
                }
                cur = bA1;
                const int rb1 = (grow + 64) * 36 + 16 * gh;
#pragma unroll
                for (int q = 0; q < 16; q++) {
                    Ap[rb1 + q] = tf32u(iscos ? cur.x : cur.y);
                    cur = cmulf(cur, S1c1);
                }
            }
            if (ls < 62) {   // bases for ls+2
                const int ch2 = (ls + 2) & 15;
                const int j2 = ((2 * ch2) & 15) + gh;
                bA0 = g_PCH[(size_t)(m0 + grow)      * 16 + j2];
                bA1 = g_PCH[(size_t)(m0 + grow + 64) * 16 + j2];
            }
        }
        // ---- MMA stage ls ----
        {
            const uint32_t* Ap = As + buf * 4608;
            const uint32_t* Bp = Bs + buf * 4352;
#pragma unroll
            for (int ks = 0; ks < 4; ks++) {
                uint32_t af[4][4];
#pragma unroll
                for (int fm = 0; fm < 4; fm++) {
                    int r = wm * 64 + fm * 16 + (lane >> 2);
                    int cb = ks * 8 + (lane & 3);
                    af[fm][0] = Ap[r * 36 + cb];
                    af[fm][1] = Ap[(r + 8) * 36 + cb];
                    af[fm][2] = Ap[r * 36 + cb + 4];
                    af[fm][3] = Ap[(r + 8) * 36 + cb + 4];
                }
#pragma unroll
                for (int fn = 0; fn < 8; fn++) {
                    int br = ks * 8 + (lane & 3);
                    int bc = wn * 64 + fn * 8 + (lane >> 2);
                    uint32_t bf[2];
                    bf[0] = Bp[br * 136 + bc];
                    bf[1] = Bp[(br + 4) * 136 + bc];
#pragma unroll
                    for (int fm = 0; fm < 4; fm++) mma8(acc[fm][fn], af[fm], bf);
                }
            }
        }
        // ---- nt boundary: fused Ey-weighted reduction, reset acc ----
        if (ch == 15) {
#pragma unroll
            for (int fm = 0; fm < 4; fm++)
#pragma unroll
            for (int cp = 0; cp < 2; cp++) {
                const int rl = wm * 64 + fm * 16 + cp * 8 + (lane >> 2);
                const int m = m0 + rl;
                const float2 S1c  = conjf(g_S1y[m]);
                const float2 S64c = conjf(g_S64y[m]);
                const float2 EYp  = g_S128y[m];
                const int a2 = ((nt & 1) << 1) | wn;
                float2 S2c = cmulf(S1c, S1c);
                float2 base = cmulf(cmulf(EYp, cpow4(S64c, a2)), cpow4(S2c, lane & 3));
                float2 S8c = cmulf(S2c, S2c); S8c = cmulf(S8c, S8c);
                float2 pb = base;
                float tx = 0.f, ty = 0.f;
#pragma unroll
                for (int fn = 0; fn < 8; fn++) {
                    float v0 = acc[fm][fn][cp * 2 + 0];
                    float v1 = acc[fm][fn][cp * 2 + 1];
                    float2 p1 = cmulf(pb, S1c);
                    if (nt < 2) { tx += v0 * pb.x + v1 * p1.x;  ty += v0 * pb.y + v1 * p1.y; }
                    else        { tx -= v0 * pb.y + v1 * p1.y;  ty += v0 * pb.x + v1 * p1.x; }
                    pb = cmulf(pb, S8c);
                }
                tx += __shfl_xor_sync(0xffffffffu, tx, 1);
                ty += __shfl_xor_sync(0xffffffffu, ty, 1);
                tx += __shfl_xor_sync(0xffffffffu, tx, 2);
                ty += __shfl_xor_sync(0xffffffffu, ty, 2);
                if ((lane & 3) == 0) {
                    t_acc[wn * 128 + rl].x += tx;
                    t_acc[wn * 128 + rl].y += ty;
                }
            }
#pragma unroll
            for (int i = 0; i < 4; i++)
#pragma unroll
                for (int j = 0; j < 8; j++)
#pragma unroll
                    for (int q = 0; q < 4; q++) acc[i][j][q] = 0.f;
        }
        if (ls < 63) asm volatile("cp.async.wait_group 0;");
        __syncthreads();
    }

    {
        const int m = m0 + tid;
        float2 t = make_float2(t_acc[tid].x + t_acc[128 + tid].x,
                               t_acc[tid].y + t_acc[128 + tid].y);
        const float lam = 1.0f / (1.0f + expf(-lamp[0]));
        const float kx = kxs[m], ky = kys[m];
        const float dcf = sqrtf(kx * kx + ky * ky);
        const int sp = m / 640, sam = m - sp * 640;
        const float2 y = yrad[sam * 288 + sp];
        const float w = lam * dcf * ORTHO;
        float2 kdc = make_float2(fmaf(w, t.x, (1.f - lam) * y.x),
                                 fmaf(w, t.y, (1.f - lam) * y.y));
        g_E0[m] = cmulf(kdc, conjf(g_S128y[m]));
    }
}

// ---------------------------------------------------------------------------
// Adjoint GEMM, software-pipelined: gen(s+1) into alt buffers overlaps MMA(s);
// one __syncthreads per stage. CTA 128u x 128n, 128 threads, warp 64x64.
// grid (split 72, ut 2, nt 4); 160 stages of 16 m (K=32).
// ---------------------------------------------------------------------------
__global__ __launch_bounds__(128)
void adj_gemm()
{
    extern __shared__ uint32_t sh[];
    uint32_t* As = sh;            // 2 x 128*36
    uint32_t* Bs = sh + 9216;     // 2 x 32*136

    const int tid = threadIdx.x, lane = tid & 31, wid = tid >> 5;
    const int wm = wid >> 1, wn = wid & 1;
    const int split = blockIdx.x, ut = blockIdx.y, nt = blockIdx.z;
    const int mb = split * ADJ_MPER;
    const int gm = tid >> 3, sub = tid & 7;
    const bool isRe = (nt < 2);
    const int yb = nt & 1;

    float acc[4][8][4];
#pragma unroll
    for (int i = 0; i < 4; i++)
#pragma unroll
        for (int j = 0; j < 8; j++)
#pragma unroll
            for (int q = 0; q < 4; q++) acc[i][j][q] = 0.f;

    // table registers for the stage about to be GENERATED
    int mp = mb + gm;
    float2 tA  = g_PXU[(size_t)mp * 16 + ut * 8 + sub];
    float2 tSx = g_S8x[mp];
    float2 tE  = g_E0[mp];
    float2 tPy = g_PYB[(size_t)mp * 16 + yb * 8 + sub];
    float2 tSy = g_S8y[mp];

    // ---- prologue: gen stage 0 into buf 0 ----
    {
        float2 curA = tA;
        float2 curB = cmulf(tE, tPy);
#pragma unroll
        for (int q = 0; q < 16; q++) {
            const int e = sub + 8 * q;
            As[e * 36 + 2 * gm]     = tf32u(curA.x);
            As[e * 36 + 2 * gm + 1] = tf32u(curA.y);
            curA = cmulf(curA, tSx);
            if (isRe) {
                Bs[(2 * gm)     * 136 + e] = tf32u(curB.x);
                Bs[(2 * gm + 1) * 136 + e] = tf32u(-curB.y);
            } else {
                Bs[(2 * gm)     * 136 + e] = tf32u(curB.y);
                Bs[(2 * gm + 1) * 136 + e] = tf32u(curB.x);
            }
            curB = cmulf(curB, tSy);
        }
    }
    mp = mb + 16 + gm;
    tA  = g_PXU[(size_t)mp * 16 + ut * 8 + sub];
    tSx = g_S8x[mp];
    tE  = g_E0[mp];
    tPy = g_PYB[(size_t)mp * 16 + yb * 8 + sub];
    tSy = g_S8y[mp];
    __syncthreads();

    for (int st = 0; st < ADJ_ST; st++) {
        const int buf = st & 1;
        // ---- gen stage st+1 into alt buffers (overlaps MMA below) ----
        if (st < ADJ_ST - 1) {
            uint32_t* Ap = As + (buf ^ 1) * 4608;
            uint32_t* Bp = Bs + (buf ^ 1) * 4352;
            float2 curA = tA;
            float2 curB = cmulf(tE, tPy);
#pragma unroll
            for (int q = 0; q < 16; q++) {
                const int e = sub + 8 * q;
                Ap[e * 36 + 2 * gm]     = tf32u(curA.x);
                Ap[e * 36 + 2 * gm + 1] = tf32u(curA.y);
                curA = cmulf(curA, tSx);
                if (isRe) {
                    Bp[(2 * gm)     * 136 + e] = tf32u(curB.x);
                    Bp[(2 * gm + 1) * 136 + e] = tf32u(-curB.y);
                } else {
                    Bp[(2 * gm)     * 136 + e] = tf32u(curB.y);
                    Bp[(2 * gm + 1) * 136 + e] = tf32u(curB.x);
                }
                curB = cmulf(curB, tSy);
            }
            if (st < ADJ_ST - 2) {   // tables for stage st+2
                mp = mb + (st + 2) * 16 + gm;
                tA  = g_PXU[(size_t)mp * 16 + ut * 8 + sub];
                tSx = g_S8x[mp];
                tE  = g_E0[mp];
                tPy = g_PYB[(size_t)mp * 16 + yb * 8 + sub];
                tSy = g_S8y[mp];
            }
        }
        // ---- MMA stage st ----
        {
            const uint32_t* Ap = As + buf * 4608;
            const uint32_t* Bp = Bs + buf * 4352;
#pragma unroll
            for (int ks = 0; ks < 4; ks++) {
                uint32_t af[4][4];
#pragma unroll
                for (int fm = 0; fm < 4; fm++) {
                    int r = wm * 64 + fm * 16 + (lane >> 2);
                    int cb = ks * 8 + (lane & 3);
                    af[fm][0] = Ap[r * 36 + cb];
                    af[fm][1] = Ap[(r + 8) * 36 + cb];
                    af[fm][2] = Ap[r * 36 + cb + 4];
                    af[fm][3] = Ap[(r + 8) * 36 + cb + 4];
                }
#pragma unroll
                for (int fn = 0; fn < 8; fn++) {
                    int br = ks * 8 + (lane & 3);
                    int bc = wn * 64 + fn * 8 + (lane >> 2);
                    uint32_t bf[2];
                    bf[0] = Bp[br * 136 + bc];
                    bf[1] = Bp[(br + 4) * 136 + bc];
#pragma unroll
                    for (int fm = 0; fm < 4; fm++) mma8(acc[fm][fn], af[fm], bf);
                }
            }
        }
        __syncthreads();
    }

    float* outp = g_P + (size_t)((ut * 4 + nt) * NSPLIT + split) * 16384;
#pragma unroll
    for (int fm = 0; fm < 4; fm++)
#pragma unroll
    for (int cp = 0; cp < 2; cp++) {
        const int u = wm * 64 + fm * 16 + cp * 8 + (lane >> 2);
#pragma unroll
        for (int fn = 0; fn < 8; fn++) {
            const int n = wn * 64 + fn * 8 + 2 * (lane & 3);
            *(float2*)&outp[u * 128 + n] =
                make_float2(acc[fm][fn][cp * 2], acc[fm][fn][cp * 2 + 1]);
        }
    }
}

// ---------------------------------------------------------------------------
__global__ __launch_bounds__(256) void reduce_k(float* __restrict__ out)
{
    const int idx = blockIdx.x * 256 + threadIdx.x;     // 0..131071
    const int ug = idx >> 9, ng = idx & 511;
    const int ut = ug >> 7, ul = ug & 127, nt = ng >> 7, nl = ng & 127;
    const float* p = g_P + (size_t)((ut * 4 + nt) * NSPLIT) * 16384 + ul * 128 + nl;
    float s = 0.f;
#pragma unroll 8
    for (int sp = 0; sp < NSPLIT; sp++) s += p[(size_t)sp * 16384];
    const int v = ng & 255, c = ng >> 8;
    out[(ug * 256 + v) * 2 + c] = s * ORTHO;
}

// ---------------------------------------------------------------------------
extern "C" void kernel_launch(void* const* d_in, const int* in_sizes, int n_in,
                              void* d_out, int out_size)
{
    const float2* img  = (const float2*)d_in[0];
    const float2* yrad = (const float2*)d_in[1];
    const float*  lamp = (const float*)d_in[2];
    const float*  ktr  = (const float*)d_in[3];
    const float*  kxs  = ktr;
    const float*  kys  = ktr + MTOT;
    float* out = (float*)d_out;

    const int FWD_SMEM = (9216 + 8704 + 512) * 4;   // 73728 B
    const int ADJ_SMEM = (9216 + 8704) * 4;         // 71680 B
    cudaFuncSetAttribute(fwd_gemm, cudaFuncAttributeMaxDynamicSharedMemorySize, FWD_SMEM);
    cudaFuncSetAttribute(adj_gemm, cudaFuncAttributeMaxDynamicSharedMemorySize, ADJ_SMEM);

    prep_tab<<<MTOT/256, 256>>>(kxs, kys);
    prep_bf<<<1024, 256>>>(img);
    fwd_gemm<<<MTOT/128, 128, FWD_SMEM>>>(yrad, lamp, kxs, kys);
    adj_gemm<<<dim3(NSPLIT, 2, 4), 128, ADJ_SMEM>>>();
    reduce_k<<<512, 256>>>(out);
}

// round 11
// speedup vs baseline: 1.0596x; 1.0596x over previous
#include <cuda_runtime.h>
#include <math.h>
#include <stdint.h>

#define IM     256
#define MTOT   184320
#define ORTHO  (1.0f/256.0f)
#define NSPLIT 72
#define ADJ_MPER (MTOT/NSPLIT)   // 2560
#define ADJ_ST   (ADJ_MPER/16)   // 160
#define NKST     (MTOT/16)       // 11520
#define NMT      (MTOT/128)      // 1440

// ---------------- static scratch -------------------------------------------
__device__ float  g_FB[4*16*4096];                  // fwd B frag tiles (1 MB)
__device__ float  g_FA[(size_t)NMT*16*4096];        // fwd A frag tiles (377 MB)
__device__ float  g_AA[(size_t)NKST*2*4096];        // adj A frag tiles (377 MB)
__device__ float2 g_S1x[MTOT], g_S8x[MTOT];
__device__ float2 g_S1y[MTOT], g_S8y[MTOT], g_S64y[MTOT], g_S128y[MTOT];
__device__ float2 g_PCH[(size_t)MTOT*16];           // conj(T0x*S16x^j)
__device__ float2 g_PXU[(size_t)MTOT*16];           // ut0: T0x*S1x^s ; ut1: S1x^s
__device__ float2 g_PYB[(size_t)MTOT*16];           // b0: S1y^s ; b1: S128y*S1y^s
__device__ float2 g_E0[MTOT];
__device__ float  g_P[(size_t)8*NSPLIT*128*128];    // adjoint partials

// ---------------- helpers --------------------------------------------------
__device__ __forceinline__ float2 cmulf(float2 a, float2 b) {
    return make_float2(a.x*b.x - a.y*b.y, a.x*b.y + a.y*b.x);
}
__device__ __forceinline__ float2 conjf(float2 a) { return make_float2(a.x, -a.y); }
__device__ __forceinline__ float tf32f(float x) {
    uint32_t r; asm("cvt.rna.tf32.f32 %0, %1;" : "=r"(r) : "f"(x));
    return __uint_as_float(r);
}
__device__ __forceinline__ float2 cpow4(float2 b, int e) {
    float2 r = make_float2(1.f, 0.f);
#pragma unroll
    for (int i = 0; i < 4; i++) { if (e & (1 << i)) r = cmulf(r, b); b = cmulf(b, b); }
    return r;
}
__device__ __forceinline__ void mma8(float* d, const uint32_t* a, const uint32_t* b) {
    asm volatile(
        "mma.sync.aligned.m16n8k8.row.col.f32.tf32.tf32.f32 "
        "{%0,%1,%2,%3}, {%4,%5,%6,%7}, {%8,%9}, {%0,%1,%2,%3};"
        : "+f"(d[0]), "+f"(d[1]), "+f"(d[2]), "+f"(d[3])
        : "r"(a[0]), "r"(a[1]), "r"(a[2]), "r"(a[3]), "r"(b[0]), "r"(b[1]));
}
__device__ __forceinline__ uint32_t su32(const void* p) {
    uint32_t a; asm("{ .reg .u64 t; cvta.to.shared.u64 t, %1; cvt.u32.u64 %0, t; }" : "=r"(a) : "l"(p));
    return a;
}
__device__ __forceinline__ void cp16(uint32_t saddr, const void* g) {
    asm volatile("cp.async.cg.shared.global [%0], [%1], 16;" :: "r"(saddr), "l"(g));
}
// A-frag float index for element (r, k) of a 128x32 tile
__device__ __forceinline__ int afidx(int r, int k) {
    int ks = k >> 3, kl = k & 3, kh = (k >> 2) & 1;
    int wm = r >> 6, fm = (r >> 4) & 3, p = (r >> 3) & 1, rr = r & 7;
    return (ks * 256 + (wm * 32 + fm * 8 + rr) * 4 + kl) * 4 + p + 2 * kh;
}
// B-frag float index for element (k, n) of a 32x128 tile
__device__ __forceinline__ int bfidx(int k, int n) {
    int ks = k >> 3, kl2 = k & 3, h = (k >> 2) & 1;
    return (ks * 512 + n * 4 + kl2) * 2 + h;
}

// ---------------- prep kernels ---------------------------------------------
__global__ __launch_bounds__(256) void prep_tab(const float* __restrict__ kxs,
                                                const float* __restrict__ kys)
{
    int m = blockIdx.x * 256 + threadIdx.x;
    float s, c;
    float kx = kxs[m], ky = kys[m];
    sincosf(kx, &s, &c);
    float2 S1 = make_float2(c, s);
    float2 S2 = cmulf(S1,S1), S4 = cmulf(S2,S2), S8 = cmulf(S4,S4);
    float2 S16 = cmulf(S8,S8), S32 = cmulf(S16,S16), S64 = cmulf(S32,S32);
    float2 S128 = cmulf(S64,S64);
    float2 T0 = conjf(S128);
    g_S1x[m] = S1; g_S8x[m] = S8;
    float2 q = T0;
#pragma unroll
    for (int j = 0; j < 16; j++) { g_PCH[(size_t)m*16 + j] = conjf(q); q = cmulf(q, S16); }
    float2 p = make_float2(1.f, 0.f);
#pragma unroll
    for (int s8 = 0; s8 < 8; s8++) {
        g_PXU[(size_t)m*16 + s8]     = cmulf(T0, p);
        g_PXU[(size_t)m*16 + 8 + s8] = p;
        p = cmulf(p, S1);
    }
    sincosf(ky, &s, &c);
    S1 = make_float2(c, s);
    S2 = cmulf(S1,S1); S4 = cmulf(S2,S2); S8 = cmulf(S4,S4);
    S16 = cmulf(S8,S8); S32 = cmulf(S16,S16); S64 = cmulf(S32,S32);
    S128 = cmulf(S64,S64);
    g_S1y[m] = S1; g_S8y[m] = S8; g_S64y[m] = S64; g_S128y[m] = S128;
    p = make_float2(1.f, 0.f);
#pragma unroll
    for (int s8 = 0; s8 < 8; s8++) {
        g_PYB[(size_t)m*16 + s8]     = p;
        g_PYB[(size_t)m*16 + 8 + s8] = cmulf(S128, p);
        p = cmulf(p, S1);
    }
}

// fwd B frag tiles from img
__global__ __launch_bounds__(256) void prep_bf(const float2* __restrict__ img)
{
    int idx = blockIdx.x * 256 + threadIdx.x;     // 0..262143
    int k = idx >> 9, n = idx & 511;
    int v = n & 255, u = k & 255;
    float2 g = img[u * 256 + v];
    float val = (n < 256) ? ((k < 256) ? g.x : -g.y)
                          : ((k < 256) ? g.y :  g.x);
    int nt = n >> 7, nn = n & 127, ch = k >> 5, kk = k & 31;
    g_FB[(nt * 16 + ch) * 4096 + bfidx(kk, nn)] = tf32f(val);
}

// fwd A frag tiles: A[m][k]: k<256 -> cos(kx u'), k>=256 -> -sin(kx u'), u=k&255
__global__ __launch_bounds__(128) void prep_fa()
{
    __shared__ float tile[4096];
    const int tid = threadIdx.x, gh = tid & 1, grow = tid >> 1;
    const int mtile = blockIdx.x, ch = blockIdx.y;
    const int m0 = mtile * 128;
    const bool iscos = (ch < 8);
    const int j = ((2 * ch) & 15) + gh;
#pragma unroll
    for (int rs = 0; rs < 2; rs++) {
        const int r = grow + 64 * rs, m = m0 + r;
        float2 cur = g_PCH[(size_t)m * 16 + j];
        const float2 st = conjf(g_S1x[m]);
#pragma unroll
        for (int q = 0; q < 16; q++) {
            tile[afidx(r, 16 * gh + q)] = tf32f(iscos ? cur.x : cur.y);
            cur = cmulf(cur, st);
        }
    }
    __syncthreads();
    float4* dst = (float4*)(g_FA + ((size_t)mtile * 16 + ch) * 4096);
    const float4* src = (const float4*)tile;
#pragma unroll
    for (int i = 0; i < 8; i++) dst[i * 128 + tid] = src[i * 128 + tid];
}

// adj A frag tiles: A[u][2m+c] = cos/sin(kx u'), u' = ut*128 + u - 128
__global__ __launch_bounds__(128) void prep_aa()
{
    __shared__ float tile[4096];
    const int tid = threadIdx.x, gm = tid >> 3, sub = tid & 7;
    const int kst = blockIdx.x, ut = blockIdx.y;
    const int m = kst * 16 + gm;
    float2 cur = g_PXU[(size_t)m * 16 + ut * 8 + sub];
    const float2 stp = g_S8x[m];
#pragma unroll
    for (int q = 0; q < 16; q++) {
        const int u = sub + 8 * q;
        tile[afidx(u, 2 * gm)]     = tf32f(cur.x);
        tile[afidx(u, 2 * gm + 1)] = tf32f(cur.y);
        cur = cmulf(cur, stp);
    }
    __syncthreads();
    float4* dst = (float4*)(g_AA + ((size_t)kst * 2 + ut) * 4096);
    const float4* src = (const float4*)tile;
#pragma unroll
    for (int i = 0; i < 8; i++) dst[i * 128 + tid] = src[i * 128 + tid];
}

// ---------------------------------------------------------------------------
// Forward GEMM: both operands cp.async (triple buffer), no in-loop gen.
// CTA 128m, 128 thr, warp 64x64; fused Ey-reduce + blend -> g_E0.
// ---------------------------------------------------------------------------
__global__ __launch_bounds__(128)
void fwd_gemm(const float2* __restrict__ yrad, const float* __restrict__ lamp,
              const float* __restrict__ kxs, const float* __restrict__ kys)
{
    extern __shared__ float sh[];
    float* As = sh;                       // 3 x 4096
    float* Bs = sh + 12288;               // 3 x 4096
    float2* t_acc = (float2*)(sh + 24576);

    const int tid = threadIdx.x, lane = tid & 31, wid = tid >> 5;
    const int wm = wid >> 1, wn = wid & 1;
    const int mtile = blockIdx.x, m0 = mtile * 128;

    t_acc[tid]       = make_float2(0.f, 0.f);
    t_acc[128 + tid] = make_float2(0.f, 0.f);

    float acc[4][8][4];
#pragma unroll
    for (int i = 0; i < 4; i++)
#pragma unroll
        for (int j = 0; j < 8; j++)
#pragma unroll
            for (int q = 0; q < 4; q++) acc[i][j][q] = 0.f;

#define FWD_FETCH(ls_) do {                                                     \
    if ((ls_) < 64) {                                                           \
        int b_ = (ls_) % 3;                                                     \
        const float* sA = g_FA + ((size_t)mtile * 16 + ((ls_) & 15)) * 4096;    \
        const float* sB = g_FB + ((((ls_) >> 4) * 16 + ((ls_) & 15))) * 4096;   \
        uint32_t dA = su32(As + b_ * 4096), dB = su32(Bs + b_ * 4096);          \
        for (int i_ = 0; i_ < 8; i_++) {                                        \
            cp16(dA + (i_ * 128 + tid) * 16, sA + (i_ * 128 + tid) * 4);        \
            cp16(dB + (i_ * 128 + tid) * 16, sB + (i_ * 128 + tid) * 4);        \
        }                                                                       \
    }                                                                           \
    asm volatile("cp.async.commit_group;");                                     \
} while (0)

    FWD_FETCH(0);
    FWD_FETCH(1);
    asm volatile("cp.async.wait_group 1;");
    __syncthreads();

    for (int ls = 0; ls < 64; ls++) {
        const int b = ls % 3, nt = ls >> 4, ch = ls & 15;
        const float4* Af = (const float4*)(As + b * 4096);
        const float2* Bf = (const float2*)(Bs + b * 4096);
#pragma unroll
        for (int ks = 0; ks < 4; ks++) {
            float4 av[4];
#pragma unroll
            for (int fm = 0; fm < 4; fm++)
                av[fm] = Af[ks * 256 + (wm * 32 + fm * 8 + (lane >> 2)) * 4 + (lane & 3)];
#pragma unroll
            for (int fn = 0; fn < 8; fn++) {
                float2 bv = Bf[ks * 512 + (wn * 64 + fn * 8 + (lane >> 2)) * 4 + (lane & 3)];
#pragma unroll
                for (int fm = 0; fm < 4; fm++)
                    mma8(acc[fm][fn], (const uint32_t*)&av[fm], (const uint32_t*)&bv);
            }
        }
        if (ch == 15) {   // fused Ey-weighted reduction for this nt
#pragma unroll
            for (int fm = 0; fm < 4; fm++)
#pragma unroll
            for (int cp = 0; cp < 2; cp++) {
                const int rl = wm * 64 + fm * 16 + cp * 8 + (lane >> 2);
                const int m = m0 + rl;
                const float2 S1c  = conjf(g_S1y[m]);
                const float2 S64c = conjf(g_S64y[m]);
                const float2 EYp  = g_S128y[m];
                const int a2 = ((nt & 1) << 1) | wn;
                float2 S2c = cmulf(S1c, S1c);
                float2 pb = cmulf(cmulf(EYp, cpow4(S64c, a2)), cpow4(S2c, lane & 3));
                float2 S8c = cmulf(S2c, S2c); S8c = cmulf(S8c, S8c);
                float tx = 0.f, ty = 0.f;
#pragma unroll
                for (int fn = 0; fn < 8; fn++) {
                    float v0 = acc[fm][fn][cp * 2 + 0];
                    float v1 = acc[fm][fn][cp * 2 + 1];
                    float2 p1 = cmulf(pb, S1c);
                    if (nt < 2) { tx += v0 * pb.x + v1 * p1.x;  ty += v0 * pb.y + v1 * p1.y; }
                    else        { tx -= v0 * pb.y + v1 * p1.y;  ty += v0 * pb.x + v1 * p1.x; }
                    pb = cmulf(pb, S8c);
                }
                tx += __shfl_xor_sync(0xffffffffu, tx, 1);
                ty += __shfl_xor_sync(0xffffffffu, ty, 1);
                tx += __shfl_xor_sync(0xffffffffu, tx, 2);
                ty += __shfl_xor_sync(0xffffffffu, ty, 2);
                if ((lane & 3) == 0) {
                    t_acc[wn * 128 + rl].x += tx;
                    t_acc[wn * 128 + rl].y += ty;
                }
            }
#pragma unroll
            for (int i = 0; i < 4; i++)
#pragma unroll
                for (int j = 0; j < 8; j++)
#pragma unroll
                    for (int q = 0; q < 4; q++) acc[i][j][q] = 0.f;
        }
        FWD_FETCH(ls + 2);
        asm volatile("cp.async.wait_group 1;");
        __syncthreads();
    }

    {
        const int m = m0 + tid;
        float2 t = make_float2(t_acc[tid].x + t_acc[128 + tid].x,
                               t_acc[tid].y + t_acc[128 + tid].y);
        const float lam = 1.0f / (1.0f + expf(-lamp[0]));
        const float kx = kxs[m], ky = kys[m];
        const float dcf = sqrtf(kx * kx + ky * ky);
        const int sp = m / 640, sam = m - sp * 640;
        const float2 y = yrad[sam * 288 + sp];
        const float w = lam * dcf * ORTHO;
        float2 kdc = make_float2(fmaf(w, t.x, (1.f - lam) * y.x),
                                 fmaf(w, t.y, (1.f - lam) * y.y));
        g_E0[m] = cmulf(kdc, conjf(g_S128y[m]));
    }
}

// ---------------------------------------------------------------------------
// Adjoint GEMM: A via cp.async (triple buffer), B generated (double buffer,
// 2 interleaved chains). One __syncthreads per stage. Warp 64x64.
// ---------------------------------------------------------------------------
__global__ __launch_bounds__(128)
void adj_gemm()
{
    extern __shared__ float sh[];
    float* As = sh;            // 3 x 4096
    float* Bs = sh + 12288;    // 2 x 4096

    const int tid = threadIdx.x, lane = tid & 31, wid = tid >> 5;
    const int wm = wid >> 1, wn = wid & 1;
    const int split = blockIdx.x, ut = blockIdx.y, nt = blockIdx.z;
    const int gm = tid >> 3, sub = tid & 7;
    const bool isRe = (nt < 2);
    const int yb = nt & 1;
    // B write float indices for k'=2gm (f0) and 2gm+1 (f1) at n: base + n*8
    const int bks = gm >> 2, bh = (gm >> 1) & 1, bkl = 2 * (gm & 1);
    const int bbase0 = (bks * 512 + bkl) * 2 + bh;        // + n*8
    const int bbase1 = (bks * 512 + bkl + 1) * 2 + bh;

    float acc[4][8][4];
#pragma unroll
    for (int i = 0; i < 4; i++)
#pragma unroll
        for (int j = 0; j < 8; j++)
#pragma unroll
            for (int q = 0; q < 4; q++) acc[i][j][q] = 0.f;

#define ADJ_FETCH(st_) do {                                                         \
    if ((st_) < ADJ_ST) {                                                           \
        int b_ = (st_) % 3;                                                         \
        const float* sA = g_AA + (((size_t)(split * ADJ_ST + (st_)) * 2) + ut) * 4096; \
        uint32_t dA = su32(As + b_ * 4096);                                         \
        for (int i_ = 0; i_ < 8; i_++)                                              \
            cp16(dA + (i_ * 128 + tid) * 16, sA + (i_ * 128 + tid) * 4);            \
    }                                                                               \
    asm volatile("cp.async.commit_group;");                                         \
} while (0)

    // table regs for the NEXT B-gen
    float2 tE, tPy, tS8;
#define ADJ_TAB(st_) do {                                                   \
    int m_ = (split * ADJ_ST + (st_)) * 16 + gm;                            \
    tE  = g_E0[m_];                                                         \
    tPy = g_PYB[(size_t)m_ * 16 + yb * 8 + sub];                            \
    tS8 = g_S8y[m_];                                                        \
} while (0)

#define ADJ_GENB(st_) do {                                                  \
    float* Bp = Bs + ((st_) & 1) * 4096;                                    \
    float2 s16 = cmulf(tS8, tS8);                                           \
    float2 c0 = cmulf(tE, tPy);                                             \
    float2 c1 = cmulf(c0, tS8);                                             \
    _Pragma("unroll")                                                       \
    for (int q2 = 0; q2 < 8; q2++) {                                        \
        int n0 = sub + 16 * q2, n1 = n0 + 8;                                \
        if (isRe) {                                                         \
            Bp[bbase0 + n0 * 8] = tf32f(c0.x);                              \
            Bp[bbase1 + n0 * 8] = tf32f(-c0.y);                             \
            Bp[bbase0 + n1 * 8] = tf32f(c1.x);                              \
            Bp[bbase1 + n1 * 8] = tf32f(-c1.y);                             \
        } else {                                                            \
            Bp[bbase0 + n0 * 8] = tf32f(c0.y);                              \
            Bp[bbase1 + n0 * 8] = tf32f(c0.x);                              \
            Bp[bbase0 + n1 * 8] = tf32f(c1.y);                              \
            Bp[bbase1 + n1 * 8] = tf32f(c1.x);                              \
        }                                                                   \
        c0 = cmulf(c0, s16);                                                \
        c1 = cmulf(c1, s16);                                                \
    }                                                                       \
} while (0)

    // prologue
    ADJ_FETCH(0);
    ADJ_FETCH(1);
    ADJ_TAB(0); ADJ_GENB(0);
    ADJ_TAB(1);
    asm volatile("cp.async.wait_group 1;");
    __syncthreads();

    for (int st = 0; st < ADJ_ST; st++) {
        // gen B(st+1) first (tables already loaded), overlaps MMA issue below
        if (st + 1 < ADJ_ST) ADJ_GENB(st + 1);
        if (st + 2 < ADJ_ST) ADJ_TAB(st + 2);
        // MMA(st)
        {
            const float4* Af = (const float4*)(As + (st % 3) * 4096);
            const float2* Bf = (const float2*)(Bs + (st & 1) * 4096);
#pragma unroll
            for (int ks = 0; ks < 4; ks++) {
                float4 av[4];
#pragma unroll
                for (int fm = 0; fm < 4; fm++)
                    av[fm] = Af[ks * 256 + (wm * 32 + fm * 8 + (lane >> 2)) * 4 + (lane & 3)];
#pragma unroll
                for (int fn = 0; fn < 8; fn++) {
                    float2 bv = Bf[ks * 512 + (wn * 64 + fn * 8 + (lane >> 2)) * 4 + (lane & 3)];
#pragma unroll
                    for (int fm = 0; fm < 4; fm++)
                        mma8(acc[fm][fn], (const uint32_t*)&av[fm], (const uint32_t*)&bv);
                }
            }
        }
        ADJ_FETCH(st + 2);
        asm volatile("cp.async.wait_group 1;");
        __syncthreads();
    }

    float* outp = g_P + (size_t)((ut * 4 + nt) * NSPLIT + split) * 16384;
#pragma unroll
    for (int fm = 0; fm < 4; fm++)
#pragma unroll
    for (int cp = 0; cp < 2; cp++) {
        const int u = wm * 64 + fm * 16 + cp * 8 + (lane >> 2);
#pragma unroll
        for (int fn = 0; fn < 8; fn++) {
            const int n = wn * 64 + fn * 8 + 2 * (lane & 3);
            *(float2*)&outp[u * 128 + n] =
                make_float2(acc[fm][fn][cp * 2], acc[fm][fn][cp * 2 + 1]);
        }
    }
}

// ---------------------------------------------------------------------------
__global__ __launch_bounds__(256) void reduce_k(float* __restrict__ out)
{
    const int idx = blockIdx.x * 256 + threadIdx.x;
    const int ug = idx >> 9, ng = idx & 511;
    const int ut = ug >> 7, ul = ug & 127, nt = ng >> 7, nl = ng & 127;
    const float* p = g_P + (size_t)((ut * 4 + nt) * NSPLIT) * 16384 + ul * 128 + nl;
    float s = 0.f;
#pragma unroll 8
    for (int sp = 0; sp < NSPLIT; sp++) s += p[(size_t)sp * 16384];
    const int v = ng & 255, c = ng >> 8;
    out[(ug * 256 + v) * 2 + c] = s * ORTHO;
}

// ---------------------------------------------------------------------------
extern "C" void kernel_launch(void* const* d_in, const int* in_sizes, int n_in,
                              void* d_out, int out_size)
{
    const float2* img  = (const float2*)d_in[0];
    const float2* yrad = (const float2*)d_in[1];
    const float*  lamp = (const float*)d_in[2];
    const float*  ktr  = (const float*)d_in[3];
    const float*  kxs  = ktr;
    const float*  kys  = ktr + MTOT;
    float* out = (float*)d_out;

    const int FWD_SMEM = (24576 + 512) * 4;    // 100352 B
    const int ADJ_SMEM = 20480 * 4;            // 81920 B
    cudaFuncSetAttribute(fwd_gemm, cudaFuncAttributeMaxDynamicSharedMemorySize, FWD_SMEM);
    cudaFuncSetAttribute(adj_gemm, cudaFuncAttributeMaxDynamicSharedMemorySize, ADJ_SMEM);

    prep_tab<<<MTOT/256, 256>>>(kxs, kys);
    prep_bf<<<1024, 256>>>(img);
    prep_fa<<<dim3(NMT, 16), 128>>>();
    prep_aa<<<dim3(NKST, 2), 128>>>();
    fwd_gemm<<<NMT, 128, FWD_SMEM>>>(yrad, lamp, kxs, kys);
    adj_gemm<<<dim3(NSPLIT, 2, 4), 128, ADJ_SMEM>>>();
    reduce_k<<<512, 256>>>(out);
}